// round 3
// baseline (speedup 1.0000x reference)
#include <cuda_runtime.h>
#include <cstdint>

// ============================================================================
// ShotHead fused kernel (GB300 / sm_100a)
//   gate  = relu(x @ Wg1 + bg1) @ Wg2 + bg2          (per row)
//   alpha = segment_softmax(gate, batch)             (batch sorted -> ranges)
//   hg    = segment_sum(alpha * x)                   ([B, 64])
//   out   = relu(hg @ Wm1 + bm1) @ Wm2 + bm2         ([B, 1])
//
// Kernel 1: segment boundaries by binary search (batch is sorted).
// Kernel 2: one CTA per segment. x rows staged in SMEM (DRAM read exactly
// once), gate via packed fma.rn.f32x2 (full-rate fp32 on Blackwell),
// block reductions for softmax, weighted sum from SMEM, head MLP in warp 0.
// ============================================================================

#define NTHREADS 256
#define MAXR     320            // SMEM x-tile capacity (rows); mean seg = 200
#define MAXN_SCRATCH 1048576

__device__ int   g_start[8193];
__device__ float g_scratch[MAXN_SCRATCH];   // overflow fallback only (len > MAXR)

// ---------------------------------------------------------------------------
// Kernel 1: segment starts via binary search. Handles int64 or int32 batch.
// ---------------------------------------------------------------------------
__global__ void seg_starts_kernel(const void* __restrict__ batch, int N, int B) {
    int b = blockIdx.x * blockDim.x + threadIdx.x;
    if (b > B) return;
    const int*       b32 = (const int*)batch;
    const long long* b64 = (const long long*)batch;
    // int64 little-endian, values < 2^31: word at odd index N-1 is the high
    // word of an element -> 0. int32: word N-1 = sorted max batch id > 0.
    bool is64 = (b32[N - 1] == 0);
    int lo = 0, hi = N;
    while (lo < hi) {
        int mid = (lo + hi) >> 1;
        long long v = is64 ? b64[mid] : (long long)b32[mid];
        if (v < (long long)b) lo = mid + 1; else hi = mid;
    }
    g_start[b] = lo;
}

// ---------------------------------------------------------------------------
// SMEM layout (floats, after the float4 x-tile)
// ---------------------------------------------------------------------------
#define XT_F4     (MAXR * 17)          /* padded tile: 17 float4 per row      */
#define OFF_W     (XT_F4 * 4)          /* Wg1: 2048 floats                    */
#define OFF_E     (OFF_W + 2048)       /* e_arr: MAXR                         */
#define OFF_WS    (OFF_E + MAXR)       /* wsum: 8*64                          */
#define OFF_HG    (OFF_WS + 512)       /* hg: 64                              */
#define OFF_RED   (OFF_HG + 64)        /* reduction scratch: 64               */
#define OFF_B1    (OFF_RED + 64)       /* bg1: 32                             */
#define OFF_W2    (OFF_B1 + 32)        /* Wg2: 32                             */
#define OFF_B2    (OFF_W2 + 32)        /* bg2 + pad: 16                       */
#define SMEM_FLOATS (OFF_B2 + 16)
#define SMEM_BYTES  (SMEM_FLOATS * 4)

// ---------------------------------------------------------------------------
// Gate MLP for one row using packed f32x2 FMAs. 16 independent f32x2
// accumulator chains; W read as 128-bit broadcast LDS (all lanes same addr,
// 16B-aligned: OFF_W is a multiple of 4 float4s and rows are 128B apart).
// ---------------------------------------------------------------------------
__device__ __forceinline__ float gate_rows_core(
    const float4* __restrict__ xr,      // 16 float4 = one x row
    const float*  __restrict__ sW,      // Wg1 [64][32] row-major
    const float*  __restrict__ sb1,     // bg1 [32]
    const float*  __restrict__ sw2,     // Wg2 [32]
    float b2)
{
    unsigned long long h2[16];          // h2[m] = hidden units (2m, 2m+1)
#pragma unroll
    for (int j = 0; j < 16; j++) h2[j] = 0ULL;

#pragma unroll 2
    for (int kq = 0; kq < 16; kq++) {
        float4 xv = xr[kq];
        float xs0 = xv.x, xs1 = xv.y, xs2 = xv.z, xs3 = xv.w;
#pragma unroll
        for (int t = 0; t < 4; t++) {
            float xk = (t == 0) ? xs0 : (t == 1) ? xs1 : (t == 2) ? xs2 : xs3;
            unsigned long long xx;
            asm("mov.b64 %0, {%1, %1};" : "=l"(xx) : "r"(__float_as_uint(xk)));
            const ulonglong2* wr = (const ulonglong2*)(sW + (kq * 4 + t) * 32);
#pragma unroll
            for (int j = 0; j < 8; j++) {
                ulonglong2 wv = wr[j];                        // LDS.128 broadcast
                asm("fma.rn.f32x2 %0, %1, %2, %0;"
                    : "+l"(h2[2 * j])     : "l"(xx), "l"(wv.x));
                asm("fma.rn.f32x2 %0, %1, %2, %0;"
                    : "+l"(h2[2 * j + 1]) : "l"(xx), "l"(wv.y));
            }
        }
    }

    float g = b2;
#pragma unroll
    for (int j = 0; j < 16; j++) {
        unsigned int lo, hi;
        asm("mov.b64 {%0, %1}, %2;" : "=r"(lo), "=r"(hi) : "l"(h2[j]));
        g += fmaxf(__uint_as_float(lo) + sb1[2 * j],     0.f) * sw2[2 * j];
        g += fmaxf(__uint_as_float(hi) + sb1[2 * j + 1], 0.f) * sw2[2 * j + 1];
    }
    return g;
}

// Cold path: row not in the SMEM tile (statistically never taken at MAXR=320).
__device__ __noinline__ float gate_row_global(
    const float* x, long long row,
    const float* sW, const float* sb1, const float* sw2, float b2)
{
    return gate_rows_core((const float4*)x + row * 16, sW, sb1, sw2, b2);
}

// ---------------------------------------------------------------------------
// Block reduction (max or sum) over 256 threads. red[] needs 33 floats.
// ---------------------------------------------------------------------------
__device__ __forceinline__ float block_reduce(float v, float* red, bool do_max) {
#pragma unroll
    for (int o = 16; o; o >>= 1) {
        float t = __shfl_xor_sync(0xffffffffu, v, o);
        v = do_max ? fmaxf(v, t) : (v + t);
    }
    if ((threadIdx.x & 31) == 0) red[threadIdx.x >> 5] = v;
    __syncthreads();
    if (threadIdx.x < 32) {
        float t2 = (threadIdx.x < 8) ? red[threadIdx.x]
                                     : (do_max ? -3.402823466e38f : 0.f);
#pragma unroll
        for (int o = 4; o; o >>= 1) {
            float t = __shfl_xor_sync(0xffffffffu, t2, o);
            t2 = do_max ? fmaxf(t2, t) : (t2 + t);
        }
        if (threadIdx.x == 0) red[32] = t2;
    }
    __syncthreads();
    float res = red[32];
    __syncthreads();          // safe reuse of red[] by the next reduction
    return res;
}

// ---------------------------------------------------------------------------
// Kernel 2: fused per-segment pipeline. Grid = B, block = 256.
// ---------------------------------------------------------------------------
__global__ void __launch_bounds__(NTHREADS, 2) shothead_fused(
    const float* __restrict__ x,
    const float* __restrict__ Wg1, const float* __restrict__ bg1,
    const float* __restrict__ Wg2, const float* __restrict__ bg2,
    const float* __restrict__ Wm1, const float* __restrict__ bm1,
    const float* __restrict__ Wm2, const float* __restrict__ bm2,
    float* __restrict__ out)
{
    extern __shared__ char smem_raw[];
    float4* xt4  = (float4*)smem_raw;
    float*  smf  = (float*)smem_raw;
    float*  sW   = smf + OFF_W;
    float*  e_arr= smf + OFF_E;
    float*  wsum = smf + OFF_WS;
    float*  hg   = smf + OFF_HG;
    float*  red  = smf + OFF_RED;
    float*  sb1  = smf + OFF_B1;
    float*  sw2  = smf + OFF_W2;
    float*  sb2  = smf + OFF_B2;

    const int tid = threadIdx.x;
    const int b   = blockIdx.x;
    const int s   = g_start[b];
    const int len = g_start[b + 1] - s;

    // ---- stage weights + x tile into SMEM (x read from DRAM exactly once) --
    for (int i = tid; i < 512; i += NTHREADS)
        ((float4*)sW)[i] = ((const float4*)Wg1)[i];
    if (tid < 32) { sb1[tid] = bg1[tid]; sw2[tid] = Wg2[tid]; }
    if (tid == 0) sb2[0] = bg2[0];

    {
        const int nload = ((len < MAXR) ? len : MAXR) * 16;
        const float4* gx = (const float4*)x + (long long)s * 16;
        for (int i = tid; i < nload; i += NTHREADS)
            xt4[(i >> 4) * 17 + (i & 15)] = gx[i];   // padded row stride: 17 f4
    }
    __syncthreads();

    const float b2v = sb2[0];

    // ---- pass 1: gate per row, track local max ----------------------------
    float g0 = 0.f, g1 = 0.f;
    float lmax = -3.402823466e38f;
    {
        int it = 0;
        for (int r = tid; r < len; r += NTHREADS, it++) {
            float g;
            if (r < MAXR)
                g = gate_rows_core(&xt4[r * 17], sW, sb1, sw2, b2v);
            else
                g = gate_row_global(x, (long long)(s + r), sW, sb1, sw2, b2v);
            if (it == 0)      g0 = g;
            else if (it == 1) g1 = g;
            else              g_scratch[s + r] = g;
            lmax = fmaxf(lmax, g);
        }
    }
    float gmax = block_reduce(lmax, red, true);

    // ---- pass 1.5: exp + local sum ----------------------------------------
    float lsum = 0.f;
    {
        int it = 0;
        for (int r = tid; r < len; r += NTHREADS, it++) {
            float g = (it == 0) ? g0 : (it == 1) ? g1 : g_scratch[s + r];
            float e = __expf(g - gmax);
            lsum += e;
            if (r < MAXR) e_arr[r] = e; else g_scratch[s + r] = e;
        }
    }
    float ssum = block_reduce(lsum, red, false);
    if (ssum == 0.f) ssum = 1.f;     // empty-segment guard (hg stays 0)

    // ---- pass 2: weighted sum  hg = sum(e * x) / ssum ---------------------
    {
        const int w = tid >> 5, l = tid & 31;
        float a0 = 0.f, a1 = 0.f;
        for (int r = w; r < len; r += 8) {
            float e, v0, v1;
            if (r < MAXR) {
                e = e_arr[r];
                const float* xr = (const float*)&xt4[r * 17];
                v0 = xr[l]; v1 = xr[l + 32];
            } else {
                e = g_scratch[s + r];
                const float* xr = x + (long long)(s + r) * 64;
                v0 = xr[l]; v1 = xr[l + 32];
            }
            a0 += e * v0; a1 += e * v1;
        }
        wsum[w * 64 + l]      = a0;
        wsum[w * 64 + l + 32] = a1;
    }
    __syncthreads();
    if (tid < 64) {
        float h = 0.f;
#pragma unroll
        for (int w = 0; w < 8; w++) h += wsum[w * 64 + tid];
        hg[tid] = h / ssum;
    }
    __syncthreads();

    // ---- pass 3: head MLP, warp 0 -----------------------------------------
    if (tid < 32) {
        float hm = 0.f;
#pragma unroll
        for (int k = 0; k < 64; k++)
            hm = fmaf(hg[k], Wm1[k * 32 + tid], hm);
        float c = fmaxf(hm + bm1[tid], 0.f) * Wm2[tid];
#pragma unroll
        for (int o = 16; o; o >>= 1) c += __shfl_xor_sync(0xffffffffu, c, o);
        if (tid == 0) out[b] = c + bm2[0];
    }
}

// ---------------------------------------------------------------------------
// Host launch (graph-capturable: kernel launches + function-attribute only)
// ---------------------------------------------------------------------------
extern "C" void kernel_launch(void* const* d_in, const int* in_sizes, int n_in,
                              void* d_out, int out_size)
{
    const float* x   = (const float*)d_in[0];
    const void*  bat = d_in[1];
    const float* Wg1 = (const float*)d_in[2];
    const float* bg1 = (const float*)d_in[3];
    const float* Wg2 = (const float*)d_in[4];
    const float* bg2 = (const float*)d_in[5];
    const float* Wm1 = (const float*)d_in[6];
    const float* bm1 = (const float*)d_in[7];
    const float* Wm2 = (const float*)d_in[8];
    const float* bm2 = (const float*)d_in[9];

    const int N = in_sizes[1];     // element count of batch
    const int B = out_size;        // one logit per segment

    seg_starts_kernel<<<(B + 1 + 255) / 256, 256>>>(bat, N, B);

    cudaFuncSetAttribute(shothead_fused,
                         cudaFuncAttributeMaxDynamicSharedMemorySize, SMEM_BYTES);
    shothead_fused<<<B, NTHREADS, SMEM_BYTES>>>(
        x, Wg1, bg1, Wg2, bg2, Wm1, bm1, Wm2, bm2, (float*)d_out);
}

// round 4
// speedup vs baseline: 1.1280x; 1.1280x over previous
#include <cuda_runtime.h>
#include <cstdint>

// ============================================================================
// ShotHead fused kernel (GB300 / sm_100a)  — round 4: register-blocked gate.
//   gate  = relu(x @ Wg1 + bg1) @ Wg2 + bg2
//   alpha = segment_softmax(gate, batch)      (batch sorted -> ranges)
//   hg    = segment_sum(alpha * x)
//   out   = relu(hg @ Wm1 + bm1) @ Wm2 + bm2
//
// Round-3 profile: kernel is L1-return-BW bound (75%): every LDS.128 broadcast
// of Wg1 delivers 512B; 8KB of W delivered per row == measured 186us.
// Fix: block 4 rows x 16 hidden per lane (half-warps split hidden), so W LDS
// is amortized over 4 rows -> 2KB/row delivered. shfl_xor(16) combines the
// two hidden halves.
// ============================================================================

#define NTHREADS 256
#define MAXR     320            // SMEM x-tile capacity (rows); mean seg = 200
#define MAXN_SCRATCH 1048576

__device__ int   g_start[8193];
__device__ float g_scratch[MAXN_SCRATCH];   // overflow fallback only (len > MAXR)

// ---------------------------------------------------------------------------
// Kernel 1: segment starts via binary search. Handles int64 or int32 batch.
// ---------------------------------------------------------------------------
__global__ void seg_starts_kernel(const void* __restrict__ batch, int N, int B) {
    int b = blockIdx.x * blockDim.x + threadIdx.x;
    if (b > B) return;
    const int*       b32 = (const int*)batch;
    const long long* b64 = (const long long*)batch;
    bool is64 = (b32[N - 1] == 0);   // int64 LE high word of last elem == 0
    int lo = 0, hi = N;
    while (lo < hi) {
        int mid = (lo + hi) >> 1;
        long long v = is64 ? b64[mid] : (long long)b32[mid];
        if (v < (long long)b) lo = mid + 1; else hi = mid;
    }
    g_start[b] = lo;
}

// ---------------------------------------------------------------------------
// SMEM layout (floats, after the float4 x-tile)
// ---------------------------------------------------------------------------
#define XT_F4     (MAXR * 17)          /* padded tile: 17 float4 per row      */
#define OFF_W     (XT_F4 * 4)          /* Wg1: 2048 floats                    */
#define OFF_E     (OFF_W + 2048)       /* g/e array: MAXR                     */
#define OFF_WS    (OFF_E + MAXR)       /* wsum: 8*64                          */
#define OFF_HG    (OFF_WS + 512)       /* hg: 64                              */
#define OFF_RED   (OFF_HG + 64)        /* reduction scratch: 64               */
#define OFF_B1    (OFF_RED + 64)       /* bg1: 32                             */
#define OFF_W2    (OFF_B1 + 32)        /* Wg2: 32                             */
#define OFF_B2    (OFF_W2 + 32)        /* bg2 + pad: 16                       */
#define SMEM_FLOATS (OFF_B2 + 16)
#define SMEM_BYTES  (SMEM_FLOATS * 4)

// ---------------------------------------------------------------------------
// Old full-row gate (used only for overflow rows >= MAXR: reads x from GMEM).
// ---------------------------------------------------------------------------
__device__ __noinline__ float gate_row_global(
    const float* x, long long row,
    const float* sW, const float* sb1, const float* sw2, float b2)
{
    const float4* xr = (const float4*)x + row * 16;
    unsigned long long h2[16];
#pragma unroll
    for (int j = 0; j < 16; j++) h2[j] = 0ULL;
    for (int kq = 0; kq < 16; kq++) {
        float4 xv = xr[kq];
        float xs[4] = {xv.x, xv.y, xv.z, xv.w};
        for (int t = 0; t < 4; t++) {
            unsigned long long xx;
            asm("mov.b64 %0, {%1, %1};" : "=l"(xx) : "r"(__float_as_uint(xs[t])));
            const ulonglong2* wr = (const ulonglong2*)(sW + (kq * 4 + t) * 32);
            for (int j = 0; j < 8; j++) {
                ulonglong2 wv = wr[j];
                asm("fma.rn.f32x2 %0, %1, %2, %0;" : "+l"(h2[2*j])   : "l"(xx), "l"(wv.x));
                asm("fma.rn.f32x2 %0, %1, %2, %0;" : "+l"(h2[2*j+1]) : "l"(xx), "l"(wv.y));
            }
        }
    }
    float g = b2;
    for (int j = 0; j < 16; j++) {
        unsigned int lo, hi;
        asm("mov.b64 {%0, %1}, %2;" : "=r"(lo), "=r"(hi) : "l"(h2[j]));
        g += fmaxf(__uint_as_float(lo) + sb1[2*j],   0.f) * sw2[2*j];
        g += fmaxf(__uint_as_float(hi) + sb1[2*j+1], 0.f) * sw2[2*j+1];
    }
    return g;
}

// ---------------------------------------------------------------------------
// Block reduction (max or sum) over 256 threads. red[] needs 33 floats.
// ---------------------------------------------------------------------------
__device__ __forceinline__ float block_reduce(float v, float* red, bool do_max) {
#pragma unroll
    for (int o = 16; o; o >>= 1) {
        float t = __shfl_xor_sync(0xffffffffu, v, o);
        v = do_max ? fmaxf(v, t) : (v + t);
    }
    if ((threadIdx.x & 31) == 0) red[threadIdx.x >> 5] = v;
    __syncthreads();
    if (threadIdx.x < 32) {
        float t2 = (threadIdx.x < 8) ? red[threadIdx.x]
                                     : (do_max ? -3.402823466e38f : 0.f);
#pragma unroll
        for (int o = 4; o; o >>= 1) {
            float t = __shfl_xor_sync(0xffffffffu, t2, o);
            t2 = do_max ? fmaxf(t2, t) : (t2 + t);
        }
        if (threadIdx.x == 0) red[32] = t2;
    }
    __syncthreads();
    float res = red[32];
    __syncthreads();
    return res;
}

// ---------------------------------------------------------------------------
// Kernel 2: fused per-segment pipeline. Grid = B, block = 256.
// ---------------------------------------------------------------------------
__global__ void __launch_bounds__(NTHREADS, 2) shothead_fused(
    const float* __restrict__ x,
    const float* __restrict__ Wg1, const float* __restrict__ bg1,
    const float* __restrict__ Wg2, const float* __restrict__ bg2,
    const float* __restrict__ Wm1, const float* __restrict__ bm1,
    const float* __restrict__ Wm2, const float* __restrict__ bm2,
    float* __restrict__ out)
{
    extern __shared__ char smem_raw[];
    float4* xt4  = (float4*)smem_raw;
    float*  smf  = (float*)smem_raw;
    float*  sW   = smf + OFF_W;
    float*  e_arr= smf + OFF_E;      // holds g, then e
    float*  wsum = smf + OFF_WS;
    float*  hg   = smf + OFF_HG;
    float*  red  = smf + OFF_RED;
    float*  sb1  = smf + OFF_B1;
    float*  sw2  = smf + OFF_W2;
    float*  sb2  = smf + OFF_B2;

    const int tid = threadIdx.x;
    const int b   = blockIdx.x;
    const int s   = g_start[b];
    const int len = g_start[b + 1] - s;
    const int lim = (len < MAXR) ? len : MAXR;

    // ---- stage weights + x tile into SMEM (x read from DRAM exactly once) --
    for (int i = tid; i < 512; i += NTHREADS)
        ((float4*)sW)[i] = ((const float4*)Wg1)[i];
    if (tid < 32) { sb1[tid] = bg1[tid]; sw2[tid] = Wg2[tid]; }
    if (tid == 0) sb2[0] = bg2[0];

    {
        const int nload = lim * 16;
        const float4* gx = (const float4*)x + (long long)s * 16;
        for (int i = tid; i < nload; i += NTHREADS)
            xt4[(i >> 4) * 17 + (i & 15)] = gx[i];   // padded row stride: 17 f4
    }
    __syncthreads();

    const float b2v = sb2[0];

    // ======================================================================
    // Gate phase: 4 rows x 16 hidden per lane. Half-warps split the hidden
    // dim (grp 0: hidden 0-15, grp 1: hidden 16-31); shfl_xor(16) combines.
    // A warp covers 64 consecutive rows per sweep; W LDS amortized 4x.
    // ======================================================================
    {
        const int w   = tid >> 5;
        const int l   = tid & 31;
        const int grp = l >> 4;          // hidden half
        const int l16 = l & 15;
        const int hb  = grp * 16;        // hidden base for this half-warp
        const float* sWh = sW + hb;

        for (int base = 0; base < lim; base += NTHREADS * 2) {   // 512 rows/sweep
            const int r0 = base + w * 64 + l16;                  // warp-uniform gate:
            if (base + w * 64 >= lim) break;                     // (w uniform per warp)

            // Clamped row offsets (rows r0 + 16*i); stores predicated below.
            int roff[4]; bool valid[4];
#pragma unroll
            for (int i = 0; i < 4; i++) {
                int r = r0 + 16 * i;
                valid[i] = (r < lim);
                int rc = valid[i] ? r : (lim - 1);
                if (rc < 0) rc = 0;
                roff[i] = rc * 17;
            }

            unsigned long long acc[4][8];
#pragma unroll
            for (int i = 0; i < 4; i++)
#pragma unroll
                for (int j = 0; j < 8; j++) acc[i][j] = 0ULL;

#pragma unroll 2
            for (int kq = 0; kq < 16; kq++) {
                float4 xv0 = xt4[roff[0] + kq];
                float4 xv1 = xt4[roff[1] + kq];
                float4 xv2 = xt4[roff[2] + kq];
                float4 xv3 = xt4[roff[3] + kq];
#pragma unroll
                for (int t = 0; t < 4; t++) {
                    float f0 = (t==0)?xv0.x:(t==1)?xv0.y:(t==2)?xv0.z:xv0.w;
                    float f1 = (t==0)?xv1.x:(t==1)?xv1.y:(t==2)?xv1.z:xv1.w;
                    float f2 = (t==0)?xv2.x:(t==1)?xv2.y:(t==2)?xv2.z:xv2.w;
                    float f3 = (t==0)?xv3.x:(t==1)?xv3.y:(t==2)?xv3.z:xv3.w;
                    unsigned long long x0, x1, x2, x3;
                    asm("mov.b64 %0, {%1, %1};" : "=l"(x0) : "r"(__float_as_uint(f0)));
                    asm("mov.b64 %0, {%1, %1};" : "=l"(x1) : "r"(__float_as_uint(f1)));
                    asm("mov.b64 %0, {%1, %1};" : "=l"(x2) : "r"(__float_as_uint(f2)));
                    asm("mov.b64 %0, {%1, %1};" : "=l"(x3) : "r"(__float_as_uint(f3)));
                    // 16 hidden for this half-warp = 4 x LDS.128
                    const ulonglong2* wr = (const ulonglong2*)(sWh + (kq*4 + t)*32);
#pragma unroll
                    for (int j = 0; j < 4; j++) {
                        ulonglong2 wv = wr[j];            // hidden hb+4j .. hb+4j+3
                        asm("fma.rn.f32x2 %0, %1, %2, %0;" : "+l"(acc[0][2*j])   : "l"(x0), "l"(wv.x));
                        asm("fma.rn.f32x2 %0, %1, %2, %0;" : "+l"(acc[0][2*j+1]) : "l"(x0), "l"(wv.y));
                        asm("fma.rn.f32x2 %0, %1, %2, %0;" : "+l"(acc[1][2*j])   : "l"(x1), "l"(wv.x));
                        asm("fma.rn.f32x2 %0, %1, %2, %0;" : "+l"(acc[1][2*j+1]) : "l"(x1), "l"(wv.y));
                        asm("fma.rn.f32x2 %0, %1, %2, %0;" : "+l"(acc[2][2*j])   : "l"(x2), "l"(wv.x));
                        asm("fma.rn.f32x2 %0, %1, %2, %0;" : "+l"(acc[2][2*j+1]) : "l"(x2), "l"(wv.y));
                        asm("fma.rn.f32x2 %0, %1, %2, %0;" : "+l"(acc[3][2*j])   : "l"(x3), "l"(wv.x));
                        asm("fma.rn.f32x2 %0, %1, %2, %0;" : "+l"(acc[3][2*j+1]) : "l"(x3), "l"(wv.y));
                    }
                }
            }

            // Epilogue: relu + Wg2 over this half's 16 hidden, combine halves.
#pragma unroll
            for (int i = 0; i < 4; i++) {
                float part = 0.f;
#pragma unroll
                for (int m = 0; m < 8; m++) {
                    unsigned int lo, hi;
                    asm("mov.b64 {%0, %1}, %2;" : "=r"(lo), "=r"(hi) : "l"(acc[i][m]));
                    part += fmaxf(__uint_as_float(lo) + sb1[hb + 2*m],     0.f) * sw2[hb + 2*m];
                    part += fmaxf(__uint_as_float(hi) + sb1[hb + 2*m + 1], 0.f) * sw2[hb + 2*m + 1];
                }
                part += __shfl_xor_sync(0xffffffffu, part, 16);
                if (grp == 0 && valid[i])
                    e_arr[r0 + 16 * i] = part + b2v;      // g stored in e_arr
            }
        }

        // Overflow rows (len > MAXR): scalar path, x from GMEM, g to scratch.
        for (int r = MAXR + tid; r < len; r += NTHREADS)
            g_scratch[s + r] = gate_row_global(x, (long long)(s + r), sW, sb1, sw2, b2v);
    }
    __syncthreads();

    // ---- softmax max ------------------------------------------------------
    float lmax = -3.402823466e38f;
    for (int r = tid; r < len; r += NTHREADS) {
        float g = (r < MAXR) ? e_arr[r] : g_scratch[s + r];
        lmax = fmaxf(lmax, g);
    }
    float gmax = block_reduce(lmax, red, true);

    // ---- exp + sum (in-place overwrite g -> e, same index per thread) -----
    float lsum = 0.f;
    for (int r = tid; r < len; r += NTHREADS) {
        float g = (r < MAXR) ? e_arr[r] : g_scratch[s + r];
        float e = __expf(g - gmax);
        lsum += e;
        if (r < MAXR) e_arr[r] = e; else g_scratch[s + r] = e;
    }
    float ssum = block_reduce(lsum, red, false);
    if (ssum == 0.f) ssum = 1.f;     // empty-segment guard (hg stays 0)

    // ---- weighted sum  hg = sum(e * x) / ssum -----------------------------
    {
        const int w = tid >> 5, l = tid & 31;
        float a0 = 0.f, a1 = 0.f;
        for (int r = w; r < len; r += 8) {
            float e, v0, v1;
            if (r < MAXR) {
                e = e_arr[r];
                const float* xr = (const float*)&xt4[r * 17];
                v0 = xr[l]; v1 = xr[l + 32];
            } else {
                e = g_scratch[s + r];
                const float* xr = x + (long long)(s + r) * 64;
                v0 = xr[l]; v1 = xr[l + 32];
            }
            a0 += e * v0; a1 += e * v1;
        }
        wsum[w * 64 + l]      = a0;
        wsum[w * 64 + l + 32] = a1;
    }
    __syncthreads();
    if (tid < 64) {
        float h = 0.f;
#pragma unroll
        for (int w = 0; w < 8; w++) h += wsum[w * 64 + tid];
        hg[tid] = h / ssum;
    }
    __syncthreads();

    // ---- head MLP, warp 0 -------------------------------------------------
    if (tid < 32) {
        float hm = 0.f;
#pragma unroll
        for (int k = 0; k < 64; k++)
            hm = fmaf(hg[k], Wm1[k * 32 + tid], hm);
        float c = fmaxf(hm + bm1[tid], 0.f) * Wm2[tid];
#pragma unroll
        for (int o = 16; o; o >>= 1) c += __shfl_xor_sync(0xffffffffu, c, o);
        if (tid == 0) out[b] = c + bm2[0];
    }
}

// ---------------------------------------------------------------------------
// Host launch (graph-capturable: kernel launches + function-attribute only)
// ---------------------------------------------------------------------------
extern "C" void kernel_launch(void* const* d_in, const int* in_sizes, int n_in,
                              void* d_out, int out_size)
{
    const float* x   = (const float*)d_in[0];
    const void*  bat = d_in[1];
    const float* Wg1 = (const float*)d_in[2];
    const float* bg1 = (const float*)d_in[3];
    const float* Wg2 = (const float*)d_in[4];
    const float* bg2 = (const float*)d_in[5];
    const float* Wm1 = (const float*)d_in[6];
    const float* bm1 = (const float*)d_in[7];
    const float* Wm2 = (const float*)d_in[8];
    const float* bm2 = (const float*)d_in[9];

    const int N = in_sizes[1];     // element count of batch
    const int B = out_size;        // one logit per segment

    seg_starts_kernel<<<(B + 1 + 255) / 256, 256>>>(bat, N, B);

    cudaFuncSetAttribute(shothead_fused,
                         cudaFuncAttributeMaxDynamicSharedMemorySize, SMEM_BYTES);
    shothead_fused<<<B, NTHREADS, SMEM_BYTES>>>(
        x, Wg1, bg1, Wg2, bg2, Wm1, bm1, Wm2, bm2, (float*)d_out);
}

// round 7
// speedup vs baseline: 1.1435x; 1.0137x over previous
#include <cuda_runtime.h>
#include <cuda_bf16.h>
#include <cstdint>

// ============================================================================
// ShotHead fused kernel (GB300 / sm_100a) — round 7: mma.sync (HMMA) gate.
// (Round-6 source re-audited + resubmitted; round-6 bench was an infra flake.)
//   gate  = relu(x @ Wg1 + bg1) @ Wg2 + bg2
//   alpha = segment_softmax(gate, batch)      (batch sorted -> ranges)
//   hg    = segment_sum(alpha * x)
//   out   = relu(hg @ Wm1 + bm1) @ Wm2 + bm2
//
// tcgen05 unavailable (toolchain emits compute_100 PTX). Gate GEMM on
// mma.sync.m16n8k16 bf16 with 3-term split (x=hi+lo, W=hi+lo; hi*hi+hi*lo+
// lo*hi; err ~2^-16). x staged once as bf16 hi/lo SW128 tiles; pass-2
// reconstructs x = hi+lo exactly from SMEM.
// ============================================================================

#define NTHREADS 256
#define MAXR     384            // 24 chunks of 16 rows; mean seg = 200, sigma ~14
#define MAXN_SCRATCH 1048576

__device__ int   g_start[8193];
__device__ float g_scratch[MAXN_SCRATCH];   // overflow fallback only (len > MAXR)

// ---------------- helpers ---------------------------------------------------
#define SW128(o) ((o) ^ (((o) >> 3) & 0x70))

__device__ __forceinline__ uint32_t smem_u32(const void* p) {
    uint32_t a;
    asm("{ .reg .u64 t; cvta.to.shared.u64 t, %1; cvt.u32.u64 %0, t; }"
        : "=r"(a) : "l"(p));
    return a;
}
// pack: upper 16 bits = bf16(hi_elem), lower 16 bits = bf16(lo_elem)
__device__ __forceinline__ uint32_t bf16x2_pack(float hi_elem, float lo_elem) {
    uint32_t r;
    asm("cvt.rn.bf16x2.f32 %0, %1, %2;" : "=r"(r) : "f"(hi_elem), "f"(lo_elem));
    return r;
}
__device__ __forceinline__ void ldsm_x4(uint32_t a, uint32_t& r0, uint32_t& r1,
                                        uint32_t& r2, uint32_t& r3) {
    asm volatile("ldmatrix.sync.aligned.m8n8.x4.shared.b16 {%0,%1,%2,%3}, [%4];"
                 : "=r"(r0), "=r"(r1), "=r"(r2), "=r"(r3) : "r"(a));
}
__device__ __forceinline__ void ldsm_x2(uint32_t a, uint32_t& r0, uint32_t& r1) {
    asm volatile("ldmatrix.sync.aligned.m8n8.x2.shared.b16 {%0,%1}, [%2];"
                 : "=r"(r0), "=r"(r1) : "r"(a));
}
__device__ __forceinline__ void mma_bf16(float* c, uint32_t a0, uint32_t a1,
                                         uint32_t a2, uint32_t a3,
                                         uint32_t b0, uint32_t b1) {
    asm volatile(
        "mma.sync.aligned.m16n8k16.row.col.f32.bf16.bf16.f32 "
        "{%0,%1,%2,%3}, {%4,%5,%6,%7}, {%8,%9}, {%0,%1,%2,%3};"
        : "+f"(c[0]), "+f"(c[1]), "+f"(c[2]), "+f"(c[3])
        : "r"(a0), "r"(a1), "r"(a2), "r"(a3), "r"(b0), "r"(b1));
}

// ---------------------------------------------------------------------------
// SMEM layout (bytes)
// ---------------------------------------------------------------------------
#define A_HI_OFF   0                         /* 384 rows x 128B bf16 (SW128)  */
#define A_LO_OFF   49152
#define W_HI_OFF   98304                     /* W[n][k]: 32 x 128B (SW128)    */
#define W_LO_OFF   102400
#define E_OFF      106496                    /* float[384] g/e                */
#define WS_OFF     108032                    /* float[512] wsum               */
#define HG_OFF     110080                    /* float[64]                     */
#define RED_OFF    110336                    /* float[34] -> pad 160B         */
#define SB1_OFF    110496                    /* float[32] bg1                 */
#define SW2_OFF    110624                    /* float[32] Wg2                 */
#define SB2_OFF    110752                    /* float bg2                     */
#define SMEM_BYTES 110784

// ---------------------------------------------------------------------------
// Kernel 1: segment starts via binary search (int64 or int32 batch).
// ---------------------------------------------------------------------------
__global__ void seg_starts_kernel(const void* __restrict__ batch, int N, int B) {
    int b = blockIdx.x * blockDim.x + threadIdx.x;
    if (b > B) return;
    const int*       b32 = (const int*)batch;
    const long long* b64 = (const long long*)batch;
    bool is64 = (b32[N - 1] == 0);
    int lo = 0, hi = N;
    while (lo < hi) {
        int mid = (lo + hi) >> 1;
        long long v = is64 ? b64[mid] : (long long)b32[mid];
        if (v < (long long)b) lo = mid + 1; else hi = mid;
    }
    g_start[b] = lo;
}

// ---------------------------------------------------------------------------
// Overflow gate (rows >= MAXR; statistically never): scalar, from GMEM.
// ---------------------------------------------------------------------------
__device__ __noinline__ float gate_row_gmem(
    const float* x, long long row,
    const float* Wg1, const float* bg1, const float* Wg2, float b2)
{
    const float* xr = x + row * 64;
    float g = b2;
    for (int h = 0; h < 32; h++) {
        float a = bg1[h];
        for (int k = 0; k < 64; k++) a = fmaf(xr[k], Wg1[k * 32 + h], a);
        g += fmaxf(a, 0.f) * Wg2[h];
    }
    return g;
}

// ---------------------------------------------------------------------------
// Block reduction (max or sum) over 256 threads. red[] needs 33 floats.
// ---------------------------------------------------------------------------
__device__ __forceinline__ float block_reduce(float v, float* red, bool do_max) {
#pragma unroll
    for (int o = 16; o; o >>= 1) {
        float t = __shfl_xor_sync(0xffffffffu, v, o);
        v = do_max ? fmaxf(v, t) : (v + t);
    }
    if ((threadIdx.x & 31) == 0) red[threadIdx.x >> 5] = v;
    __syncthreads();
    if (threadIdx.x < 32) {
        float t2 = (threadIdx.x < 8) ? red[threadIdx.x]
                                     : (do_max ? -3.402823466e38f : 0.f);
#pragma unroll
        for (int o = 4; o; o >>= 1) {
            float t = __shfl_xor_sync(0xffffffffu, t2, o);
            t2 = do_max ? fmaxf(t2, t) : (t2 + t);
        }
        if (threadIdx.x == 0) red[32] = t2;
    }
    __syncthreads();
    float res = red[32];
    __syncthreads();
    return res;
}

// ---------------------------------------------------------------------------
// Kernel 2: fused per-segment pipeline. Grid = B, block = 256.
// ---------------------------------------------------------------------------
__global__ void __launch_bounds__(NTHREADS, 2) shothead_mma(
    const float* __restrict__ x,
    const float* __restrict__ Wg1, const float* __restrict__ bg1,
    const float* __restrict__ Wg2, const float* __restrict__ bg2,
    const float* __restrict__ Wm1, const float* __restrict__ bm1,
    const float* __restrict__ Wm2, const float* __restrict__ bm2,
    float* __restrict__ out)
{
    extern __shared__ char smem[];
    const uint32_t sb = smem_u32(smem);
    float* e_arr = (float*)(smem + E_OFF);
    float* wsum  = (float*)(smem + WS_OFF);
    float* hg    = (float*)(smem + HG_OFF);
    float* red   = (float*)(smem + RED_OFF);
    float* sb1   = (float*)(smem + SB1_OFF);
    float* sw2   = (float*)(smem + SW2_OFF);
    float* sb2   = (float*)(smem + SB2_OFF);

    const int tid = threadIdx.x;
    const int wid = tid >> 5;
    const int lid = tid & 31;
    const int b   = blockIdx.x;
    const int s   = g_start[b];
    const int len = g_start[b + 1] - s;
    const int lim = (len < MAXR) ? len : MAXR;

    // ---- W -> bf16 hi/lo tiles, layout Wn[n][k], 128B rows, SW128 ---------
    for (int idx = tid; idx < 2048; idx += NTHREADS) {
        int n = idx & 31, k = idx >> 5;            // idx == k*32+n (coalesced)
        float v = Wg1[idx];
        __nv_bfloat16 hb = __float2bfloat16(v);
        float hf = __bfloat162float(hb);
        __nv_bfloat16 lb = __float2bfloat16(v - hf);
        uint32_t off = SW128((uint32_t)(n * 128 + k * 2));
        *(unsigned short*)(smem + W_HI_OFF + off) = __bfloat16_as_ushort(hb);
        *(unsigned short*)(smem + W_LO_OFF + off) = __bfloat16_as_ushort(lb);
    }
    if (tid < 32) { sb1[tid] = bg1[tid]; sw2[tid] = Wg2[tid]; }
    if (tid == 0) sb2[0] = bg2[0];

    // ---- x -> bf16 hi/lo tiles, 128B rows, SW128 (DRAM read exactly once) -
    {
        const float4* gx = (const float4*)x + (long long)s * 16;
        const int nload = lim * 16;
        for (int i = tid; i < nload; i += NTHREADS) {
            int row = i >> 4, q = i & 15;
            float4 v = gx[i];
            uint32_t h0 = bf16x2_pack(v.y, v.x);      // elem0 low, elem1 high
            uint32_t h1 = bf16x2_pack(v.w, v.z);
            float hf0 = __uint_as_float(h0 << 16);
            float hf1 = __uint_as_float(h0 & 0xffff0000u);
            float hf2 = __uint_as_float(h1 << 16);
            float hf3 = __uint_as_float(h1 & 0xffff0000u);
            uint32_t l0 = bf16x2_pack(v.y - hf1, v.x - hf0);
            uint32_t l1 = bf16x2_pack(v.w - hf3, v.z - hf2);
            uint32_t off = SW128((uint32_t)(row * 128 + q * 8));
            *(unsigned long long*)(smem + A_HI_OFF + off) =
                (unsigned long long)h0 | ((unsigned long long)h1 << 32);
            *(unsigned long long*)(smem + A_LO_OFF + off) =
                (unsigned long long)l0 | ((unsigned long long)l1 << 32);
        }
    }
    __syncthreads();

    const float b2v = sb2[0];

    // ======================================================================
    // Gate: 16-row chunks via mma.sync m16n8k16 bf16, 3-term split.
    // ======================================================================
    for (int c = wid; c * 16 < lim; c += 8) {
        const int R0 = c * 16;
        // A frags: lanes 0-15 -> rows R0+(l&15), k-half 0; 16-31 -> k-half 1.
        const uint32_t arow   = (uint32_t)(R0 + (lid & 15));
        const uint32_t achalf = (uint32_t)(lid >> 4);
        // B frags: lanes 0-7 -> matrix0 (k-half 0), 8-15 -> matrix1 (k-half 1).
        const uint32_t bn0    = (uint32_t)(lid & 7);
        const uint32_t bchalf = (uint32_t)((lid >> 3) & 1);

        float acc[4][4];
#pragma unroll
        for (int nt = 0; nt < 4; nt++)
#pragma unroll
            for (int j = 0; j < 4; j++) acc[nt][j] = 0.f;

#pragma unroll
        for (int kk = 0; kk < 4; kk++) {
            uint32_t a_off = SW128(arow * 128 + (2 * kk + achalf) * 16);
            uint32_t ah0, ah1, ah2, ah3, al0, al1, al2, al3;
            ldsm_x4(sb + A_HI_OFF + a_off, ah0, ah1, ah2, ah3);
            ldsm_x4(sb + A_LO_OFF + a_off, al0, al1, al2, al3);
#pragma unroll
            for (int nt = 0; nt < 4; nt++) {
                uint32_t w_off = SW128((bn0 + nt * 8) * 128 + (2 * kk + bchalf) * 16);
                uint32_t bh0, bh1, bl0, bl1;
                ldsm_x2(sb + W_HI_OFF + w_off, bh0, bh1);
                ldsm_x2(sb + W_LO_OFF + w_off, bl0, bl1);
                mma_bf16(acc[nt], ah0, ah1, ah2, ah3, bh0, bh1);  // hi*hi
                mma_bf16(acc[nt], ah0, ah1, ah2, ah3, bl0, bl1);  // hi*lo
                mma_bf16(acc[nt], al0, al1, al2, al3, bh0, bh1);  // lo*hi
            }
        }

        // Epilogue: g = relu(h + bg1).Wg2 (+bg2), rows r=l/4 and r+8.
        float pr = 0.f, pr8 = 0.f;
#pragma unroll
        for (int nt = 0; nt < 4; nt++) {
            int c0 = nt * 8 + 2 * (lid & 3);
            float b10 = sb1[c0], b11 = sb1[c0 + 1];
            float w20 = sw2[c0], w21 = sw2[c0 + 1];
            pr  += fmaxf(acc[nt][0] + b10, 0.f) * w20
                 + fmaxf(acc[nt][1] + b11, 0.f) * w21;
            pr8 += fmaxf(acc[nt][2] + b10, 0.f) * w20
                 + fmaxf(acc[nt][3] + b11, 0.f) * w21;
        }
#pragma unroll
        for (int o = 1; o <= 2; o <<= 1) {
            pr  += __shfl_xor_sync(0xffffffffu, pr,  o);
            pr8 += __shfl_xor_sync(0xffffffffu, pr8, o);
        }
        if ((lid & 3) == 0) {
            int r = R0 + (lid >> 2);
            if (r < lim)     e_arr[r]     = pr  + b2v;
            if (r + 8 < lim) e_arr[r + 8] = pr8 + b2v;
        }
    }

    // Overflow rows (len > MAXR; statistically never).
    for (int r = MAXR + tid; r < len; r += NTHREADS)
        g_scratch[s + r] = gate_row_gmem(x, (long long)(s + r), Wg1, bg1, Wg2, b2v);
    __syncthreads();

    // ---- softmax max ------------------------------------------------------
    float lmax = -3.402823466e38f;
    for (int r = tid; r < len; r += NTHREADS) {
        float g = (r < MAXR) ? e_arr[r] : g_scratch[s + r];
        lmax = fmaxf(lmax, g);
    }
    float gmax = block_reduce(lmax, red, true);

    // ---- exp + sum --------------------------------------------------------
    float lsum = 0.f;
    for (int r = tid; r < len; r += NTHREADS) {
        float g = (r < MAXR) ? e_arr[r] : g_scratch[s + r];
        float e = __expf(g - gmax);
        lsum += e;
        if (r < MAXR) e_arr[r] = e; else g_scratch[s + r] = e;
    }
    float ssum = block_reduce(lsum, red, false);
    if (ssum == 0.f) ssum = 1.f;

    // ---- weighted sum: hg = sum(e * (x_hi + x_lo)) / ssum -----------------
    {
        const int w = tid >> 5, l = tid & 31;     // lane l covers k = 2l, 2l+1
        float a0 = 0.f, a1 = 0.f;
        for (int r = w; r < len; r += 8) {
            float e, x0, x1;
            if (r < MAXR) {
                e = e_arr[r];
                uint32_t off = SW128((uint32_t)(r * 128 + l * 4));
                uint32_t hw = *(uint32_t*)(smem + A_HI_OFF + off);
                uint32_t lw = *(uint32_t*)(smem + A_LO_OFF + off);
                x0 = __uint_as_float(hw << 16)         + __uint_as_float(lw << 16);
                x1 = __uint_as_float(hw & 0xffff0000u) + __uint_as_float(lw & 0xffff0000u);
            } else {
                e = g_scratch[s + r];
                const float* xr = x + (long long)(s + r) * 64;
                x0 = xr[2 * l]; x1 = xr[2 * l + 1];
            }
            a0 += e * x0; a1 += e * x1;
        }
        wsum[w * 64 + 2 * l]     = a0;
        wsum[w * 64 + 2 * l + 1] = a1;
    }
    __syncthreads();
    if (tid < 64) {
        float h = 0.f;
#pragma unroll
        for (int w = 0; w < 8; w++) h += wsum[w * 64 + tid];
        hg[tid] = h / ssum;
    }
    __syncthreads();

    // ---- head MLP, warp 0 -------------------------------------------------
    if (tid < 32) {
        float hm = 0.f;
#pragma unroll
        for (int k = 0; k < 64; k++)
            hm = fmaf(hg[k], Wm1[k * 32 + tid], hm);
        float c = fmaxf(hm + bm1[tid], 0.f) * Wm2[tid];
#pragma unroll
        for (int o = 16; o; o >>= 1) c += __shfl_xor_sync(0xffffffffu, c, o);
        if (tid == 0) out[b] = c + bm2[0];
    }
}

// ---------------------------------------------------------------------------
// Host launch (graph-capturable)
// ---------------------------------------------------------------------------
extern "C" void kernel_launch(void* const* d_in, const int* in_sizes, int n_in,
                              void* d_out, int out_size)
{
    const float* x   = (const float*)d_in[0];
    const void*  bat = d_in[1];
    const float* Wg1 = (const float*)d_in[2];
    const float* bg1 = (const float*)d_in[3];
    const float* Wg2 = (const float*)d_in[4];
    const float* bg2 = (const float*)d_in[5];
    const float* Wm1 = (const float*)d_in[6];
    const float* bm1 = (const float*)d_in[7];
    const float* Wm2 = (const float*)d_in[8];
    const float* bm2 = (const float*)d_in[9];

    const int N = in_sizes[1];
    const int B = out_size;

    seg_starts_kernel<<<(B + 1 + 255) / 256, 256>>>(bat, N, B);

    cudaFuncSetAttribute(shothead_mma,
                         cudaFuncAttributeMaxDynamicSharedMemorySize, SMEM_BYTES);
    shothead_mma<<<B, NTHREADS, SMEM_BYTES>>>(
        x, Wg1, bg1, Wg2, bg2, Wm1, bm1, Wm2, bm2, (float*)d_out);
}

// round 8
// speedup vs baseline: 1.7909x; 1.5662x over previous
#include <cuda_runtime.h>
#include <cuda_bf16.h>
#include <cstdint>

// ============================================================================
// ShotHead (GB300 / sm_100a) — round 8: streaming-chunk design.
//   gate  = relu(x @ Wg1 + bg1) @ Wg2 + bg2
//   alpha = segment_softmax(gate, batch)   == e^g / seg_sum(e^g)  (shift-inv.)
//   hg    = segment_sum(alpha * x)
//   out   = relu(hg @ Wm1 + bm1) @ Wm2 + bm2
//
// Round-7 lesson: latency/occupancy-bound (all pipes <42%, occ 23%).
// Fix: CTA = 128-row chunk (not a segment), 44KB SMEM -> 4 CTAs/SM;
// single-pass segment accumulation (no softmax max), per-piece atomicAdd.
// Gate on mma.sync m16n8k16 bf16, 3-term split, A-frags converted in regs.
// ============================================================================

#define TILE     128
#define NT       256
#define XPITCH   68          // floats per x row in SMEM (17 float4, pad)
#define MAXB     8192

__device__ float g_num[MAXB * 64];
__device__ float g_den[MAXB];

// ---------------- helpers ---------------------------------------------------
__device__ __forceinline__ uint32_t bf16x2_pack(float hi_elem, float lo_elem) {
    uint32_t r;   // low 16 = lo_elem, high 16 = hi_elem
    asm("cvt.rn.bf16x2.f32 %0, %1, %2;" : "=r"(r) : "f"(hi_elem), "f"(lo_elem));
    return r;
}
__device__ __forceinline__ void mma_bf16(float* c, uint32_t a0, uint32_t a1,
                                         uint32_t a2, uint32_t a3,
                                         uint32_t b0, uint32_t b1) {
    asm volatile(
        "mma.sync.aligned.m16n8k16.row.col.f32.bf16.bf16.f32 "
        "{%0,%1,%2,%3}, {%4,%5,%6,%7}, {%8,%9}, {%0,%1,%2,%3};"
        : "+f"(c[0]), "+f"(c[1]), "+f"(c[2]), "+f"(c[3])
        : "r"(a0), "r"(a1), "r"(a2), "r"(a3), "r"(b0), "r"(b1));
}

// ---------------------------------------------------------------------------
// SMEM layout (bytes).  WPITCH = 72 bf16 = 144 B (4n-bank shift: conflict-free)
// ---------------------------------------------------------------------------
#define X_OFF    0                          /* 128 x 272B fp32               */
#define WH_OFF   34816                      /* Whi[n][k] 32 x 144B           */
#define WL_OFF   39424                      /* Wlo[n][k] 32 x 144B           */
#define E_OFF    44032                      /* float[128] e                  */
#define BT_OFF   44544                      /* int[128] segment ids          */
#define SB1_OFF  45056                      /* float[32] bg1                 */
#define SW2_OFF  45184                      /* float[32] Wg2                 */
#define SMEM_BYTES 45312

// ---------------------------------------------------------------------------
// Kernel 0: zero accumulators.
// ---------------------------------------------------------------------------
__global__ void zero_kernel(int B) {
    int i = blockIdx.x * blockDim.x + threadIdx.x;
    if (i < B * 64) g_num[i] = 0.f;
    if (i < B)      g_den[i] = 0.f;
}

// ---------------------------------------------------------------------------
// Kernel 1: per-chunk gate + e + segmented partial sums. Grid = ceil(N/128).
// ---------------------------------------------------------------------------
__global__ void __launch_bounds__(NT, 4) shothead_chunk(
    const float* __restrict__ x, const void* __restrict__ batch,
    const float* __restrict__ Wg1, const float* __restrict__ bg1,
    const float* __restrict__ Wg2, const float* __restrict__ bg2,
    int N, int B)
{
    extern __shared__ char smem[];
    float* xs    = (float*)(smem + X_OFF);
    float* e_arr = (float*)(smem + E_OFF);
    int*   sbat  = (int*)  (smem + BT_OFF);
    float* sb1   = (float*)(smem + SB1_OFF);
    float* sw2   = (float*)(smem + SW2_OFF);

    const int tid = threadIdx.x;
    const int wid = tid >> 5;
    const int lid = tid & 31;
    const long long row0 = (long long)blockIdx.x * TILE;
    const int nrows = (N - row0 < TILE) ? (int)(N - row0) : TILE;

    // ---- stage W -> bf16 hi/lo, layout [n][k] pitch 72 bf16 ---------------
    for (int idx = tid; idx < 2048; idx += NT) {
        int n = idx & 31, k = idx >> 5;            // idx == k*32+n (coalesced)
        float v = Wg1[idx];
        __nv_bfloat16 hb = __float2bfloat16(v);
        float hf = __bfloat162float(hb);
        __nv_bfloat16 lb = __float2bfloat16(v - hf);
        *(unsigned short*)(smem + WH_OFF + n * 144 + k * 2) = __bfloat16_as_ushort(hb);
        *(unsigned short*)(smem + WL_OFF + n * 144 + k * 2) = __bfloat16_as_ushort(lb);
    }
    if (tid < 32) { sb1[tid] = bg1[tid]; sw2[tid] = Wg2[tid]; }

    // ---- stage x fp32 (read from DRAM exactly once) + batch ids -----------
    {
        const float4* gx = (const float4*)x + row0 * 16;
        const int nload = nrows * 16;
        for (int i = tid; i < nload; i += NT) {
            float4 v = gx[i];
            ((float4*)(xs + (i >> 4) * XPITCH))[i & 15] = v;
        }
        const int*       b32 = (const int*)batch;
        const long long* b64 = (const long long*)batch;
        bool is64 = (b32[N - 1] == 0);
        for (int i = tid; i < TILE; i += NT)
            sbat[i] = (i < nrows)
                    ? (is64 ? (int)b64[row0 + i] : b32[row0 + i]) : -1;
    }
    __syncthreads();

    const float b2v = __ldg(&bg2[0]);

    // ======================================================================
    // Gate: warp w handles rows [16w, 16w+16). A-frags from fp32 SMEM,
    // converted to bf16 hi/lo in registers. 3-term mma (hi*hi+hi*lo+lo*hi).
    // ======================================================================
    {
        const int R0  = wid * 16;
        const int grp = lid >> 2;                 // row within chunk half
        const int tig = lid & 3;                  // k-pair selector
        const float* xr  = xs + (R0 + grp) * XPITCH + tig * 2;
        const float* xr8 = xr + 8 * XPITCH;

        float acc[4][4];
#pragma unroll
        for (int nt = 0; nt < 4; nt++)
#pragma unroll
            for (int j = 0; j < 4; j++) acc[nt][j] = 0.f;

#pragma unroll
        for (int kk = 0; kk < 4; kk++) {
            const int kb = kk * 16;
            float2 p00 = *(const float2*)(xr  + kb);       // a0: row g,   k lo
            float2 p01 = *(const float2*)(xr8 + kb);       // a1: row g+8, k lo
            float2 p10 = *(const float2*)(xr  + kb + 8);   // a2: row g,   k hi
            float2 p11 = *(const float2*)(xr8 + kb + 8);   // a3: row g+8, k hi
            uint32_t ah0 = bf16x2_pack(p00.y, p00.x);
            uint32_t ah1 = bf16x2_pack(p01.y, p01.x);
            uint32_t ah2 = bf16x2_pack(p10.y, p10.x);
            uint32_t ah3 = bf16x2_pack(p11.y, p11.x);
            uint32_t al0 = bf16x2_pack(p00.y - __uint_as_float(ah0 & 0xffff0000u),
                                       p00.x - __uint_as_float(ah0 << 16));
            uint32_t al1 = bf16x2_pack(p01.y - __uint_as_float(ah1 & 0xffff0000u),
                                       p01.x - __uint_as_float(ah1 << 16));
            uint32_t al2 = bf16x2_pack(p10.y - __uint_as_float(ah2 & 0xffff0000u),
                                       p10.x - __uint_as_float(ah2 << 16));
            uint32_t al3 = bf16x2_pack(p11.y - __uint_as_float(ah3 & 0xffff0000u),
                                       p11.x - __uint_as_float(ah3 << 16));
#pragma unroll
            for (int nt = 0; nt < 4; nt++) {
                // B-frag: lane -> n = nt*8 + grp, k = tig*2 (+8 for b1)
                const char* wrh = smem + WH_OFF + (nt * 8 + grp) * 144 + kb * 2 + tig * 4;
                const char* wrl = smem + WL_OFF + (nt * 8 + grp) * 144 + kb * 2 + tig * 4;
                uint32_t bh0 = *(const uint32_t*)wrh;
                uint32_t bh1 = *(const uint32_t*)(wrh + 16);
                uint32_t bl0 = *(const uint32_t*)wrl;
                uint32_t bl1 = *(const uint32_t*)(wrl + 16);
                mma_bf16(acc[nt], ah0, ah1, ah2, ah3, bh0, bh1);  // hi*hi
                mma_bf16(acc[nt], ah0, ah1, ah2, ah3, bl0, bl1);  // hi*lo
                mma_bf16(acc[nt], al0, al1, al2, al3, bh0, bh1);  // lo*hi
            }
        }

        // Epilogue: g = relu(h+bg1).Wg2 + bg2 -> e = exp(g); rows g, g+8.
        float pr = 0.f, pr8 = 0.f;
#pragma unroll
        for (int nt = 0; nt < 4; nt++) {
            int c0 = nt * 8 + 2 * tig;
            float b10 = sb1[c0], b11 = sb1[c0 + 1];
            float w20 = sw2[c0], w21 = sw2[c0 + 1];
            pr  += fmaxf(acc[nt][0] + b10, 0.f) * w20
                 + fmaxf(acc[nt][1] + b11, 0.f) * w21;
            pr8 += fmaxf(acc[nt][2] + b10, 0.f) * w20
                 + fmaxf(acc[nt][3] + b11, 0.f) * w21;
        }
#pragma unroll
        for (int o = 1; o <= 2; o <<= 1) {
            pr  += __shfl_xor_sync(0xffffffffu, pr,  o);
            pr8 += __shfl_xor_sync(0xffffffffu, pr8, o);
        }
        if (tig == 0) {
            e_arr[R0 + grp]     = __expf(fminf(pr  + b2v, 80.f));
            e_arr[R0 + grp + 8] = __expf(fminf(pr8 + b2v, 80.f));
        }
    }
    __syncthreads();

    // ======================================================================
    // Segmented accumulation: 4 groups x 64 cols; group q scans rows
    // [32q, 32q+32), flushing (seg-piece) partials with atomicAdd.
    // ======================================================================
    {
        const int q   = tid >> 6;
        const int col = tid & 63;
        const int rb  = q * 32;
        float acc = 0.f, eacc = 0.f;
        int cur = sbat[rb];
#pragma unroll 4
        for (int i = 0; i < 32; i++) {
            int r  = rb + i;
            int sg = sbat[r];
            if (sg != cur) {
                if (cur >= 0) {
                    atomicAdd(&g_num[(long long)cur * 64 + col], acc);
                    if (col == 0) atomicAdd(&g_den[cur], eacc);
                }
                acc = 0.f; eacc = 0.f; cur = sg;
            }
            float e = e_arr[r];
            acc += e * xs[r * XPITCH + col];
            if (col == 0) eacc += e;
        }
        if (cur >= 0) {
            atomicAdd(&g_num[(long long)cur * 64 + col], acc);
            if (col == 0) atomicAdd(&g_den[cur], eacc);
        }
    }
}

// ---------------------------------------------------------------------------
// Kernel 2: head MLP. Warp per segment; 8 segments per 256-thr block.
// ---------------------------------------------------------------------------
__global__ void __launch_bounds__(256) shothead_head(
    const float* __restrict__ Wm1, const float* __restrict__ bm1,
    const float* __restrict__ Wm2, const float* __restrict__ bm2,
    float* __restrict__ out, int B)
{
    __shared__ float sW[2048];
    __shared__ float shg[8][64];
    const int tid = threadIdx.x;
    const int wid = tid >> 5;
    const int lid = tid & 31;

    for (int i = tid; i < 2048; i += 256) sW[i] = Wm1[i];
    __syncthreads();

    const int seg = blockIdx.x * 8 + wid;
    if (seg < B) {
        float d = g_den[seg];
        if (d == 0.f) d = 1.f;
        float inv = 1.f / d;
        shg[wid][lid]      = g_num[(long long)seg * 64 + lid]      * inv;
        shg[wid][lid + 32] = g_num[(long long)seg * 64 + lid + 32] * inv;
        __syncwarp();

        float hm = 0.f;
#pragma unroll
        for (int k = 0; k < 64; k++)
            hm = fmaf(shg[wid][k], sW[k * 32 + lid], hm);
        float c = fmaxf(hm + __ldg(&bm1[lid]), 0.f) * __ldg(&Wm2[lid]);
#pragma unroll
        for (int o = 16; o; o >>= 1) c += __shfl_xor_sync(0xffffffffu, c, o);
        if (lid == 0) out[seg] = c + __ldg(&bm2[0]);
    }
}

// ---------------------------------------------------------------------------
// Host launch (graph-capturable: 3 kernel launches)
// ---------------------------------------------------------------------------
extern "C" void kernel_launch(void* const* d_in, const int* in_sizes, int n_in,
                              void* d_out, int out_size)
{
    const float* x   = (const float*)d_in[0];
    const void*  bat = d_in[1];
    const float* Wg1 = (const float*)d_in[2];
    const float* bg1 = (const float*)d_in[3];
    const float* Wg2 = (const float*)d_in[4];
    const float* bg2 = (const float*)d_in[5];
    const float* Wm1 = (const float*)d_in[6];
    const float* bm1 = (const float*)d_in[7];
    const float* Wm2 = (const float*)d_in[8];
    const float* bm2 = (const float*)d_in[9];

    const int N = in_sizes[1];     // rows
    const int B = out_size;        // segments

    zero_kernel<<<(B * 64 + 255) / 256, 256>>>(B);

    const int nchunks = (N + TILE - 1) / TILE;
    shothead_chunk<<<nchunks, NT, SMEM_BYTES>>>(x, bat, Wg1, bg1, Wg2, bg2, N, B);

    shothead_head<<<(B + 7) / 8, 256>>>(Wm1, bm1, Wm2, bm2, (float*)d_out, B);
}

// round 9
// speedup vs baseline: 2.1566x; 1.2042x over previous
#include <cuda_runtime.h>
#include <cuda_bf16.h>
#include <cstdint>

// ============================================================================
// ShotHead (GB300 / sm_100a) — round 9: streaming chunks + cp.async staging.
//   gate  = relu(x @ Wg1 + bg1) @ Wg2 + bg2
//   alpha = e^g / seg_sum(e^g)          (shift-invariant softmax, single pass)
//   hg    = segment_sum(alpha * x)
//   out   = relu(hg @ Wm1 + bm1) @ Wm2 + bm2
//
// vs round 8 (108.5us): W bf16 hi/lo image precomputed once in a prep kernel
// (CTAs cp.async 9KB instead of 2048 cvt chains); x staged via cp.async
// (no LDG->reg->STS); accumulator zeroing folded into the head kernel
// (self-cleaning across graph replays; device globals start zeroed).
// ============================================================================

#define TILE     128
#define NT       256
#define XPITCH   68          // floats per x row in SMEM (17 float4, pad)
#define MAXB     8192

__device__ float g_num[MAXB * 64];
__device__ float g_den[MAXB];
__device__ __align__(16) unsigned char g_Wblob[9216];   // Whi(4608B) | Wlo(4608B)

// ---------------- helpers ---------------------------------------------------
__device__ __forceinline__ uint32_t smem_u32(const void* p) {
    uint32_t a;
    asm("{ .reg .u64 t; cvta.to.shared.u64 t, %1; cvt.u32.u64 %0, t; }"
        : "=r"(a) : "l"(p));
    return a;
}
__device__ __forceinline__ void cp_async16(uint32_t dst, const void* src) {
    asm volatile("cp.async.cg.shared.global [%0], [%1], 16;"
                 :: "r"(dst), "l"(src) : "memory");
}
__device__ __forceinline__ void cp_async_wait_all() {
    asm volatile("cp.async.commit_group;\n\tcp.async.wait_group 0;" ::: "memory");
}
__device__ __forceinline__ uint32_t bf16x2_pack(float hi_elem, float lo_elem) {
    uint32_t r;   // low 16 = lo_elem, high 16 = hi_elem
    asm("cvt.rn.bf16x2.f32 %0, %1, %2;" : "=r"(r) : "f"(hi_elem), "f"(lo_elem));
    return r;
}
__device__ __forceinline__ void mma_bf16(float* c, uint32_t a0, uint32_t a1,
                                         uint32_t a2, uint32_t a3,
                                         uint32_t b0, uint32_t b1) {
    asm volatile(
        "mma.sync.aligned.m16n8k16.row.col.f32.bf16.bf16.f32 "
        "{%0,%1,%2,%3}, {%4,%5,%6,%7}, {%8,%9}, {%0,%1,%2,%3};"
        : "+f"(c[0]), "+f"(c[1]), "+f"(c[2]), "+f"(c[3])
        : "r"(a0), "r"(a1), "r"(a2), "r"(a3), "r"(b0), "r"(b1));
}

// ---------------------------------------------------------------------------
// SMEM layout (bytes). W pitch = 72 bf16 = 144 B.
// WH/WL contiguous so one cp.async region covers both.
// ---------------------------------------------------------------------------
#define X_OFF    0                          /* 128 x 272B fp32               */
#define WH_OFF   34816                      /* Whi[n][k] 32 x 144B           */
#define WL_OFF   39424                      /* Wlo[n][k] 32 x 144B           */
#define E_OFF    44032                      /* float[128] e                  */
#define BT_OFF   44544                      /* int[128] segment ids          */
#define SB1_OFF  45056                      /* float[32] bg1                 */
#define SW2_OFF  45184                      /* float[32] Wg2                 */
#define SMEM_BYTES 45312

// ---------------------------------------------------------------------------
// Kernel 0 (prep): Wg1 -> bf16 hi/lo blob, SMEM-image layout [n][k] pitch 144B.
// ---------------------------------------------------------------------------
__global__ void prep_kernel(const float* __restrict__ Wg1) {
    int idx = blockIdx.x * blockDim.x + threadIdx.x;
    if (idx < 2048) {
        int n = idx & 31, k = idx >> 5;           // idx == k*32+n
        float v = Wg1[idx];
        __nv_bfloat16 hb = __float2bfloat16(v);
        float hf = __bfloat162float(hb);
        __nv_bfloat16 lb = __float2bfloat16(v - hf);
        *(unsigned short*)(g_Wblob + n * 144 + k * 2)        = __bfloat16_as_ushort(hb);
        *(unsigned short*)(g_Wblob + 4608 + n * 144 + k * 2) = __bfloat16_as_ushort(lb);
    }
}

// ---------------------------------------------------------------------------
// Kernel 1: per-chunk gate + e + segmented partial sums. Grid = ceil(N/128).
// ---------------------------------------------------------------------------
__global__ void __launch_bounds__(NT, 4) shothead_chunk(
    const float* __restrict__ x, const void* __restrict__ batch,
    const float* __restrict__ bg1, const float* __restrict__ Wg2,
    const float* __restrict__ bg2, int N, int B)
{
    extern __shared__ char smem[];
    const uint32_t sbu = smem_u32(smem);
    float* xs    = (float*)(smem + X_OFF);
    float* e_arr = (float*)(smem + E_OFF);
    int*   sbat  = (int*)  (smem + BT_OFF);
    float* sb1   = (float*)(smem + SB1_OFF);
    float* sw2   = (float*)(smem + SW2_OFF);

    const int tid = threadIdx.x;
    const int wid = tid >> 5;
    const int lid = tid & 31;
    const long long row0 = (long long)blockIdx.x * TILE;
    const int nrows = (N - row0 < TILE) ? (int)(N - row0) : TILE;

    // ---- stage x + W via cp.async (x read from DRAM exactly once) ---------
    {
        const float4* gx = (const float4*)x + row0 * 16;
        const int nload = nrows * 16;
        for (int i = tid; i < nload; i += NT)
            cp_async16(sbu + X_OFF + (i >> 4) * (XPITCH * 4) + (i & 15) * 16,
                       gx + i);
        for (int i = tid; i < 576; i += NT)                  // 9216B W image
            cp_async16(sbu + WH_OFF + i * 16, g_Wblob + i * 16);

        const int*       b32 = (const int*)batch;
        const long long* b64 = (const long long*)batch;
        bool is64 = (b32[N - 1] == 0);
        for (int i = tid; i < TILE; i += NT)
            sbat[i] = (i < nrows)
                    ? (is64 ? (int)b64[row0 + i] : b32[row0 + i]) : -1;
        if (tid < 32) { sb1[tid] = bg1[tid]; sw2[tid] = Wg2[tid]; }
        cp_async_wait_all();
    }
    __syncthreads();

    const float b2v = __ldg(&bg2[0]);

    // ======================================================================
    // Gate: warp w handles rows [16w, 16w+16). A-frags from fp32 SMEM,
    // converted to bf16 hi/lo in registers. 3-term mma (hi*hi+hi*lo+lo*hi).
    // ======================================================================
    {
        const int R0  = wid * 16;
        const int grp = lid >> 2;                 // row within chunk half
        const int tig = lid & 3;                  // k-pair selector
        const float* xr  = xs + (R0 + grp) * XPITCH + tig * 2;
        const float* xr8 = xr + 8 * XPITCH;

        float acc[4][4];
#pragma unroll
        for (int nt = 0; nt < 4; nt++)
#pragma unroll
            for (int j = 0; j < 4; j++) acc[nt][j] = 0.f;

#pragma unroll
        for (int kk = 0; kk < 4; kk++) {
            const int kb = kk * 16;
            float2 p00 = *(const float2*)(xr  + kb);       // a0: row g,   k lo
            float2 p01 = *(const float2*)(xr8 + kb);       // a1: row g+8, k lo
            float2 p10 = *(const float2*)(xr  + kb + 8);   // a2: row g,   k hi
            float2 p11 = *(const float2*)(xr8 + kb + 8);   // a3: row g+8, k hi
            uint32_t ah0 = bf16x2_pack(p00.y, p00.x);
            uint32_t ah1 = bf16x2_pack(p01.y, p01.x);
            uint32_t ah2 = bf16x2_pack(p10.y, p10.x);
            uint32_t ah3 = bf16x2_pack(p11.y, p11.x);
            uint32_t al0 = bf16x2_pack(p00.y - __uint_as_float(ah0 & 0xffff0000u),
                                       p00.x - __uint_as_float(ah0 << 16));
            uint32_t al1 = bf16x2_pack(p01.y - __uint_as_float(ah1 & 0xffff0000u),
                                       p01.x - __uint_as_float(ah1 << 16));
            uint32_t al2 = bf16x2_pack(p10.y - __uint_as_float(ah2 & 0xffff0000u),
                                       p10.x - __uint_as_float(ah2 << 16));
            uint32_t al3 = bf16x2_pack(p11.y - __uint_as_float(ah3 & 0xffff0000u),
                                       p11.x - __uint_as_float(ah3 << 16));
#pragma unroll
            for (int nt = 0; nt < 4; nt++) {
                // B-frag: lane -> n = nt*8 + grp, k = tig*2 (+8 for b1)
                const char* wrh = smem + WH_OFF + (nt * 8 + grp) * 144 + kb * 2 + tig * 4;
                const char* wrl = smem + WL_OFF + (nt * 8 + grp) * 144 + kb * 2 + tig * 4;
                uint32_t bh0 = *(const uint32_t*)wrh;
                uint32_t bh1 = *(const uint32_t*)(wrh + 16);
                uint32_t bl0 = *(const uint32_t*)wrl;
                uint32_t bl1 = *(const uint32_t*)(wrl + 16);
                mma_bf16(acc[nt], ah0, ah1, ah2, ah3, bh0, bh1);  // hi*hi
                mma_bf16(acc[nt], ah0, ah1, ah2, ah3, bl0, bl1);  // hi*lo
                mma_bf16(acc[nt], al0, al1, al2, al3, bh0, bh1);  // lo*hi
            }
        }

        // Epilogue: g = relu(h+bg1).Wg2 + bg2 -> e = exp(g); rows g, g+8.
        float pr = 0.f, pr8 = 0.f;
#pragma unroll
        for (int nt = 0; nt < 4; nt++) {
            int c0 = nt * 8 + 2 * tig;
            float b10 = sb1[c0], b11 = sb1[c0 + 1];
            float w20 = sw2[c0], w21 = sw2[c0 + 1];
            pr  += fmaxf(acc[nt][0] + b10, 0.f) * w20
                 + fmaxf(acc[nt][1] + b11, 0.f) * w21;
            pr8 += fmaxf(acc[nt][2] + b10, 0.f) * w20
                 + fmaxf(acc[nt][3] + b11, 0.f) * w21;
        }
#pragma unroll
        for (int o = 1; o <= 2; o <<= 1) {
            pr  += __shfl_xor_sync(0xffffffffu, pr,  o);
            pr8 += __shfl_xor_sync(0xffffffffu, pr8, o);
        }
        if (tig == 0) {
            e_arr[R0 + grp]     = __expf(fminf(pr  + b2v, 80.f));
            e_arr[R0 + grp + 8] = __expf(fminf(pr8 + b2v, 80.f));
        }
    }
    __syncthreads();

    // ======================================================================
    // Segmented accumulation: 4 groups x 64 cols; group q scans rows
    // [32q, 32q+32), flushing (seg-piece) partials with atomicAdd.
    // ======================================================================
    {
        const int q   = tid >> 6;
        const int col = tid & 63;
        const int rb  = q * 32;
        float acc = 0.f, eacc = 0.f;
        int cur = sbat[rb];
#pragma unroll 4
        for (int i = 0; i < 32; i++) {
            int r  = rb + i;
            int sg = sbat[r];
            if (sg != cur) {
                if (cur >= 0) {
                    atomicAdd(&g_num[(long long)cur * 64 + col], acc);
                    if (col == 0) atomicAdd(&g_den[cur], eacc);
                }
                acc = 0.f; eacc = 0.f; cur = sg;
            }
            float e = e_arr[r];
            acc += e * xs[r * XPITCH + col];
            if (col == 0) eacc += e;
        }
        if (cur >= 0) {
            atomicAdd(&g_num[(long long)cur * 64 + col], acc);
            if (col == 0) atomicAdd(&g_den[cur], eacc);
        }
    }
}

// ---------------------------------------------------------------------------
// Kernel 2: head MLP (+ self-clean accumulators for the next call/replay).
// Warp per segment; 8 segments per 256-thr block.
// ---------------------------------------------------------------------------
__global__ void __launch_bounds__(256) shothead_head(
    const float* __restrict__ Wm1, const float* __restrict__ bm1,
    const float* __restrict__ Wm2, const float* __restrict__ bm2,
    float* __restrict__ out, int B)
{
    __shared__ float sW[2048];
    __shared__ float shg[8][64];
    const int tid = threadIdx.x;
    const int wid = tid >> 5;
    const int lid = tid & 31;

    for (int i = tid; i < 2048; i += 256) sW[i] = Wm1[i];
    __syncthreads();

    const int seg = blockIdx.x * 8 + wid;
    if (seg < B) {
        float d = g_den[seg];
        if (d == 0.f) d = 1.f;
        float inv = 1.f / d;
        float n0 = g_num[(long long)seg * 64 + lid];
        float n1 = g_num[(long long)seg * 64 + lid + 32];
        shg[wid][lid]      = n0 * inv;
        shg[wid][lid + 32] = n1 * inv;
        // self-clean: zero accumulators for the next launch/replay
        g_num[(long long)seg * 64 + lid]      = 0.f;
        g_num[(long long)seg * 64 + lid + 32] = 0.f;
        if (lid == 0) g_den[seg] = 0.f;
        __syncwarp();

        float hm = 0.f;
#pragma unroll
        for (int k = 0; k < 64; k++)
            hm = fmaf(shg[wid][k], sW[k * 32 + lid], hm);
        float c = fmaxf(hm + __ldg(&bm1[lid]), 0.f) * __ldg(&Wm2[lid]);
#pragma unroll
        for (int o = 16; o; o >>= 1) c += __shfl_xor_sync(0xffffffffu, c, o);
        if (lid == 0) out[seg] = c + __ldg(&bm2[0]);
    }
}

// ---------------------------------------------------------------------------
// Host launch (graph-capturable: 3 kernel launches)
// ---------------------------------------------------------------------------
extern "C" void kernel_launch(void* const* d_in, const int* in_sizes, int n_in,
                              void* d_out, int out_size)
{
    const float* x   = (const float*)d_in[0];
    const void*  bat = d_in[1];
    const float* Wg1 = (const float*)d_in[2];
    const float* bg1 = (const float*)d_in[3];
    const float* Wg2 = (const float*)d_in[4];
    const float* bg2 = (const float*)d_in[5];
    const float* Wm1 = (const float*)d_in[6];
    const float* bm1 = (const float*)d_in[7];
    const float* Wm2 = (const float*)d_in[8];
    const float* bm2 = (const float*)d_in[9];

    const int N = in_sizes[1];     // rows
    const int B = out_size;        // segments

    prep_kernel<<<8, 256>>>(Wg1);

    const int nchunks = (N + TILE - 1) / TILE;
    shothead_chunk<<<nchunks, NT, SMEM_BYTES>>>(x, bat, bg1, Wg2, bg2, N, B);

    shothead_head<<<(B + 7) / 8, 256>>>(Wm1, bm1, Wm2, bm2, (float*)d_out, B);
}

// round 10
// speedup vs baseline: 2.4023x; 1.1139x over previous
#include <cuda_runtime.h>
#include <cuda_bf16.h>
#include <cstdint>

// ============================================================================
// ShotHead (GB300 / sm_100a) — round 10: issue-count reduction.
//   gate  = relu(x @ Wg1 + bg1) @ Wg2 + bg2
//   alpha = e^g / seg_sum(e^g)          (shift-invariant softmax, single pass)
//   hg    = segment_sum(alpha * x)
//   out   = relu(hg @ Wm1 + bm1) @ Wm2 + bm2
//
// vs round 9 (90.1us): (1) segmented accumulation vectorized: 8 strips x 16
// rows, float2 per thread, boundary-free fast path (~1792 -> ~700 warp-instr
// per CTA); (2) prep kernel removed — W bf16 hi/lo conversion inlined in
// coalesced k-pair form (2 launches total now).
// ============================================================================

#define TILE     128
#define NT       256
#define XPITCH   68          // floats per x row in SMEM (17 float4, pad)
#define MAXB     8192

__device__ float g_num[MAXB * 64];
__device__ float g_den[MAXB];

// ---------------- helpers ---------------------------------------------------
__device__ __forceinline__ uint32_t smem_u32(const void* p) {
    uint32_t a;
    asm("{ .reg .u64 t; cvta.to.shared.u64 t, %1; cvt.u32.u64 %0, t; }"
        : "=r"(a) : "l"(p));
    return a;
}
__device__ __forceinline__ void cp_async16(uint32_t dst, const void* src) {
    asm volatile("cp.async.cg.shared.global [%0], [%1], 16;"
                 :: "r"(dst), "l"(src) : "memory");
}
__device__ __forceinline__ void cp_async_wait_all() {
    asm volatile("cp.async.commit_group;\n\tcp.async.wait_group 0;" ::: "memory");
}
__device__ __forceinline__ uint32_t bf16x2_pack(float hi_elem, float lo_elem) {
    uint32_t r;   // low 16 = lo_elem, high 16 = hi_elem
    asm("cvt.rn.bf16x2.f32 %0, %1, %2;" : "=r"(r) : "f"(hi_elem), "f"(lo_elem));
    return r;
}
__device__ __forceinline__ void mma_bf16(float* c, uint32_t a0, uint32_t a1,
                                         uint32_t a2, uint32_t a3,
                                         uint32_t b0, uint32_t b1) {
    asm volatile(
        "mma.sync.aligned.m16n8k16.row.col.f32.bf16.bf16.f32 "
        "{%0,%1,%2,%3}, {%4,%5,%6,%7}, {%8,%9}, {%0,%1,%2,%3};"
        : "+f"(c[0]), "+f"(c[1]), "+f"(c[2]), "+f"(c[3])
        : "r"(a0), "r"(a1), "r"(a2), "r"(a3), "r"(b0), "r"(b1));
}

// ---------------------------------------------------------------------------
// SMEM layout (bytes). W pitch = 72 bf16 = 144 B.
// ---------------------------------------------------------------------------
#define X_OFF    0                          /* 128 x 272B fp32               */
#define WH_OFF   34816                      /* Whi[n][k] 32 x 144B           */
#define WL_OFF   39424                      /* Wlo[n][k] 32 x 144B           */
#define E_OFF    44032                      /* float[128] e                  */
#define BT_OFF   44544                      /* int[128] segment ids          */
#define SB1_OFF  45056                      /* float[32] bg1                 */
#define SW2_OFF  45184                      /* float[32] Wg2                 */
#define SMEM_BYTES 45312

// ---------------------------------------------------------------------------
// Kernel 1: per-chunk gate + e + segmented partial sums. Grid = ceil(N/128).
// ---------------------------------------------------------------------------
__global__ void __launch_bounds__(NT, 4) shothead_chunk(
    const float* __restrict__ x, const void* __restrict__ batch,
    const float* __restrict__ Wg1, const float* __restrict__ bg1,
    const float* __restrict__ Wg2, const float* __restrict__ bg2,
    int N, int B)
{
    extern __shared__ char smem[];
    const uint32_t sbu = smem_u32(smem);
    float* xs    = (float*)(smem + X_OFF);
    float* e_arr = (float*)(smem + E_OFF);
    int*   sbat  = (int*)  (smem + BT_OFF);
    float* sb1   = (float*)(smem + SB1_OFF);
    float* sw2   = (float*)(smem + SW2_OFF);

    const int tid = threadIdx.x;
    const int wid = tid >> 5;
    const int lid = tid & 31;
    const long long row0 = (long long)blockIdx.x * TILE;
    const int nrows = (N - row0 < TILE) ? (int)(N - row0) : TILE;

    // ---- stage x via cp.async (x read from DRAM exactly once) -------------
    {
        const float4* gx = (const float4*)x + row0 * 16;
        const int nload = nrows * 16;
        for (int i = tid; i < nload; i += NT)
            cp_async16(sbu + X_OFF + (i >> 4) * (XPITCH * 4) + (i & 15) * 16,
                       gx + i);
    }

    // ---- W -> bf16 hi/lo in SMEM, coalesced k-pair form (overlaps cp.async)
    for (int p = tid; p < 1024; p += NT) {
        int n = p & 31, kp = p >> 5;           // k-pair kp -> k = 2kp, 2kp+1
        float v0 = Wg1[(2 * kp) * 32 + n];
        float v1 = Wg1[(2 * kp + 1) * 32 + n];
        uint32_t h = bf16x2_pack(v1, v0);
        uint32_t lo = bf16x2_pack(v1 - __uint_as_float(h & 0xffff0000u),
                                  v0 - __uint_as_float(h << 16));
        *(uint32_t*)(smem + WH_OFF + n * 144 + kp * 4) = h;
        *(uint32_t*)(smem + WL_OFF + n * 144 + kp * 4) = lo;
    }

    // ---- batch ids + biases ----------------------------------------------
    {
        const int*       b32 = (const int*)batch;
        const long long* b64 = (const long long*)batch;
        bool is64 = (b32[N - 1] == 0);
        for (int i = tid; i < TILE; i += NT)
            sbat[i] = (i < nrows)
                    ? (is64 ? (int)b64[row0 + i] : b32[row0 + i]) : -1;
        if (tid < 32) { sb1[tid] = bg1[tid]; sw2[tid] = Wg2[tid]; }
        cp_async_wait_all();
    }
    __syncthreads();

    const float b2v = __ldg(&bg2[0]);

    // ======================================================================
    // Gate: warp w handles rows [16w, 16w+16). A-frags from fp32 SMEM,
    // converted to bf16 hi/lo in registers. 3-term mma (hi*hi+hi*lo+lo*hi).
    // ======================================================================
    {
        const int R0  = wid * 16;
        const int grp = lid >> 2;                 // row within chunk half
        const int tig = lid & 3;                  // k-pair selector
        const float* xr  = xs + (R0 + grp) * XPITCH + tig * 2;
        const float* xr8 = xr + 8 * XPITCH;

        float acc[4][4];
#pragma unroll
        for (int nt = 0; nt < 4; nt++)
#pragma unroll
            for (int j = 0; j < 4; j++) acc[nt][j] = 0.f;

#pragma unroll
        for (int kk = 0; kk < 4; kk++) {
            const int kb = kk * 16;
            float2 p00 = *(const float2*)(xr  + kb);       // a0: row g,   k lo
            float2 p01 = *(const float2*)(xr8 + kb);       // a1: row g+8, k lo
            float2 p10 = *(const float2*)(xr  + kb + 8);   // a2: row g,   k hi
            float2 p11 = *(const float2*)(xr8 + kb + 8);   // a3: row g+8, k hi
            uint32_t ah0 = bf16x2_pack(p00.y, p00.x);
            uint32_t ah1 = bf16x2_pack(p01.y, p01.x);
            uint32_t ah2 = bf16x2_pack(p10.y, p10.x);
            uint32_t ah3 = bf16x2_pack(p11.y, p11.x);
            uint32_t al0 = bf16x2_pack(p00.y - __uint_as_float(ah0 & 0xffff0000u),
                                       p00.x - __uint_as_float(ah0 << 16));
            uint32_t al1 = bf16x2_pack(p01.y - __uint_as_float(ah1 & 0xffff0000u),
                                       p01.x - __uint_as_float(ah1 << 16));
            uint32_t al2 = bf16x2_pack(p10.y - __uint_as_float(ah2 & 0xffff0000u),
                                       p10.x - __uint_as_float(ah2 << 16));
            uint32_t al3 = bf16x2_pack(p11.y - __uint_as_float(ah3 & 0xffff0000u),
                                       p11.x - __uint_as_float(ah3 << 16));
#pragma unroll
            for (int nt = 0; nt < 4; nt++) {
                // B-frag: lane -> n = nt*8 + grp, k = tig*2 (+8 for b1)
                const char* wrh = smem + WH_OFF + (nt * 8 + grp) * 144 + kb * 2 + tig * 4;
                const char* wrl = smem + WL_OFF + (nt * 8 + grp) * 144 + kb * 2 + tig * 4;
                uint32_t bh0 = *(const uint32_t*)wrh;
                uint32_t bh1 = *(const uint32_t*)(wrh + 16);
                uint32_t bl0 = *(const uint32_t*)wrl;
                uint32_t bl1 = *(const uint32_t*)(wrl + 16);
                mma_bf16(acc[nt], ah0, ah1, ah2, ah3, bh0, bh1);  // hi*hi
                mma_bf16(acc[nt], ah0, ah1, ah2, ah3, bl0, bl1);  // hi*lo
                mma_bf16(acc[nt], al0, al1, al2, al3, bh0, bh1);  // lo*hi
            }
        }

        // Epilogue: g = relu(h+bg1).Wg2 + bg2 -> e = exp(g); rows g, g+8.
        float pr = 0.f, pr8 = 0.f;
#pragma unroll
        for (int nt = 0; nt < 4; nt++) {
            int c0 = nt * 8 + 2 * tig;
            float b10 = sb1[c0], b11 = sb1[c0 + 1];
            float w20 = sw2[c0], w21 = sw2[c0 + 1];
            pr  += fmaxf(acc[nt][0] + b10, 0.f) * w20
                 + fmaxf(acc[nt][1] + b11, 0.f) * w21;
            pr8 += fmaxf(acc[nt][2] + b10, 0.f) * w20
                 + fmaxf(acc[nt][3] + b11, 0.f) * w21;
        }
#pragma unroll
        for (int o = 1; o <= 2; o <<= 1) {
            pr  += __shfl_xor_sync(0xffffffffu, pr,  o);
            pr8 += __shfl_xor_sync(0xffffffffu, pr8, o);
        }
        if (tig == 0) {
            e_arr[R0 + grp]     = __expf(fminf(pr  + b2v, 80.f));
            e_arr[R0 + grp + 8] = __expf(fminf(pr8 + b2v, 80.f));
        }
    }
    __syncthreads();

    // ======================================================================
    // Segmented accumulation: 8 strips x 16 rows; thread = float2 col pair.
    // Fast path when the strip has no segment boundary (common case).
    // ======================================================================
    {
        const int st = tid >> 5;           // strip 0..7
        const int l  = tid & 31;
        const int rb = st * 16;
        const int c2 = l * 2;
        const int first = sbat[rb], last = sbat[rb + 15];

        if (first == last) {
            if (first >= 0) {
                float a0 = 0.f, a1 = 0.f, eacc = 0.f;
#pragma unroll
                for (int i = 0; i < 16; i++) {
                    float e  = e_arr[rb + i];
                    float2 v = *(const float2*)(xs + (rb + i) * XPITCH + c2);
                    a0 += e * v.x; a1 += e * v.y; eacc += e;
                }
                atomicAdd(&g_num[(long long)first * 64 + c2],     a0);
                atomicAdd(&g_num[(long long)first * 64 + c2 + 1], a1);
                if (l == 0) atomicAdd(&g_den[first], eacc);
            }
        } else {
            float a0 = 0.f, a1 = 0.f, eacc = 0.f;
            int cur = first;
            for (int i = 0; i < 16; i++) {
                int r  = rb + i;
                int sg = sbat[r];
                if (sg != cur) {
                    if (cur >= 0) {
                        atomicAdd(&g_num[(long long)cur * 64 + c2],     a0);
                        atomicAdd(&g_num[(long long)cur * 64 + c2 + 1], a1);
                        if (l == 0) atomicAdd(&g_den[cur], eacc);
                    }
                    a0 = a1 = eacc = 0.f; cur = sg;
                }
                float e  = e_arr[r];
                float2 v = *(const float2*)(xs + r * XPITCH + c2);
                a0 += e * v.x; a1 += e * v.y; eacc += e;
            }
            if (cur >= 0) {
                atomicAdd(&g_num[(long long)cur * 64 + c2],     a0);
                atomicAdd(&g_num[(long long)cur * 64 + c2 + 1], a1);
                if (l == 0) atomicAdd(&g_den[cur], eacc);
            }
        }
    }
}

// ---------------------------------------------------------------------------
// Kernel 2: head MLP (+ self-clean accumulators for the next call/replay).
// Warp per segment; 8 segments per 256-thr block.
// ---------------------------------------------------------------------------
__global__ void __launch_bounds__(256) shothead_head(
    const float* __restrict__ Wm1, const float* __restrict__ bm1,
    const float* __restrict__ Wm2, const float* __restrict__ bm2,
    float* __restrict__ out, int B)
{
    __shared__ float sW[2048];
    __shared__ float shg[8][64];
    const int tid = threadIdx.x;
    const int wid = tid >> 5;
    const int lid = tid & 31;

    for (int i = tid; i < 2048; i += 256) sW[i] = Wm1[i];
    __syncthreads();

    const int seg = blockIdx.x * 8 + wid;
    if (seg < B) {
        float d = g_den[seg];
        if (d == 0.f) d = 1.f;
        float inv = 1.f / d;
        float n0 = g_num[(long long)seg * 64 + lid];
        float n1 = g_num[(long long)seg * 64 + lid + 32];
        shg[wid][lid]      = n0 * inv;
        shg[wid][lid + 32] = n1 * inv;
        // self-clean: zero accumulators for the next launch/replay
        g_num[(long long)seg * 64 + lid]      = 0.f;
        g_num[(long long)seg * 64 + lid + 32] = 0.f;
        if (lid == 0) g_den[seg] = 0.f;
        __syncwarp();

        float hm = 0.f;
#pragma unroll
        for (int k = 0; k < 64; k++)
            hm = fmaf(shg[wid][k], sW[k * 32 + lid], hm);
        float c = fmaxf(hm + __ldg(&bm1[lid]), 0.f) * __ldg(&Wm2[lid]);
#pragma unroll
        for (int o = 16; o; o >>= 1) c += __shfl_xor_sync(0xffffffffu, c, o);
        if (lid == 0) out[seg] = c + __ldg(&bm2[0]);
    }
}

// ---------------------------------------------------------------------------
// Host launch (graph-capturable: 2 kernel launches)
// ---------------------------------------------------------------------------
extern "C" void kernel_launch(void* const* d_in, const int* in_sizes, int n_in,
                              void* d_out, int out_size)
{
    const float* x   = (const float*)d_in[0];
    const void*  bat = d_in[1];
    const float* Wg1 = (const float*)d_in[2];
    const float* bg1 = (const float*)d_in[3];
    const float* Wg2 = (const float*)d_in[4];
    const float* bg2 = (const float*)d_in[5];
    const float* Wm1 = (const float*)d_in[6];
    const float* bm1 = (const float*)d_in[7];
    const float* Wm2 = (const float*)d_in[8];
    const float* bm2 = (const float*)d_in[9];

    const int N = in_sizes[1];     // rows
    const int B = out_size;        // segments

    const int nchunks = (N + TILE - 1) / TILE;
    shothead_chunk<<<nchunks, NT, SMEM_BYTES>>>(x, bat, Wg1, bg1, Wg2, bg2, N, B);

    shothead_head<<<(B + 7) / 8, 256>>>(Wm1, bm1, Wm2, bm2, (float*)d_out, B);
}